// round 17
// baseline (speedup 1.0000x reference)
#include <cuda_runtime.h>

// HybridLoss: smooth_l1(preds,targets) + 0.5*(1 - mean(box_overlap))
// preds, targets: [2000000, 10] float32 row-major. Output: 1 float scalar.
//
// Persistent kernel (592 CTAs x 256 thr, 4 CTA/SM) + dynamic work stealing
// with 512-row units consumed as two pipelined 256-row sub-blocks:
// one atomic + one __syncthreads per 512 rows; a load phase always overlaps
// a math phase (sub1 loads under sub0 math, next-unit sub0 loads under
// sub1 math). 40 data regs, same as the static R12 design.

#define NROWS 2000000
#define THREADS 256
#define NBLOCKS 592                                   // 148 SMs * 4 CTAs
#define UNIT_ROWS 512
#define NUNITS ((NROWS + UNIT_ROWS - 1) / UNIT_ROWS)  // 3907 (last = 128 rows)
#define EPSF 1e-6f

__device__ double g_acc[2] = {0.0, 0.0};
__device__ unsigned int g_ticket = 0;
__device__ unsigned int g_work = NBLOCKS;             // units 0..NBLOCKS-1 pre-assigned

__device__ __forceinline__ void load_row(const float2* __restrict__ p2,
                                         const float2* __restrict__ t2,
                                         int row, float2* bp, float2* bt)
{
    const float2* rp = p2 + (size_t)row * 5;   // 40B rows -> 5 float2
    const float2* rt = t2 + (size_t)row * 5;
    #pragma unroll
    for (int j = 0; j < 5; j++) { bp[j] = rp[j]; bt[j] = rt[j]; }
}

__device__ __forceinline__ void row_math(const float2* __restrict__ bp,
                                         const float2* __restrict__ bt,
                                         float& l1_acc, float& ov_acc)
{
    float p[10], t[10];
    #pragma unroll
    for (int j = 0; j < 5; j++) {
        p[2*j] = bp[j].x; p[2*j+1] = bp[j].y;
        t[2*j] = bt[j].x; t[2*j+1] = bt[j].y;
    }

    // smooth L1, select-free
    #pragma unroll
    for (int j = 0; j < 10; j++) {
        float d  = p[j] - t[j];
        float ad = fabsf(d);
        float m  = fminf(ad, 1.0f);
        l1_acc = fmaf(m, fmaf(-0.5f, m, ad), l1_acc);
    }

    // raw quaternions (no normalization)
    const float px = p[6], py = p[7], pz = p[8], pw = p[9];
    const float gx = t[6], gy = t[7], gz = t[8], gw = t[9];
    const float Ap = px*px + py*py + pz*pz + pw*pw;
    const float Ag = gx*gx + gy*gy + gz*gz + gw*gw;
    const float rpg = __fdividef(1.0f, Ap * Ag);
    const float sp  = 0.5f * Ag * rpg;   // 0.5/Ap
    const float sg  = 0.5f * Ap * rpg;   // 0.5/Ag

    const float dq = px*gx + py*gy + pz*gz + pw*gw;
    const float rot_align = fmaxf(fmaf(4.0f * dq * dq, rpg, -1.0f) * (1.0f/3.0f), 0.0f);

    const float dpx = p[3], dpy = p[4], dpz = p[5];
    const float dgx = t[3], dgy = t[4], dgz = t[5];

    float num = 1.0f, den = 1.0f;
    {
        float mp = (Ap - 2.0f*(py*py + pz*pz))*dpx + 2.0f*(px*py + pz*pw)*dpy + 2.0f*(px*pz - py*pw)*dpz;
        float mg = (Ag - 2.0f*(gy*gy + gz*gz))*dgx + 2.0f*(gx*gy + gz*gw)*dgy + 2.0f*(gx*gz - gy*gw)*dgz;
        float pe = sp * fabsf(mp), ge = sg * fabsf(mg);
        float cd = fabsf(p[0] - t[0]);
        num *= fmaxf(2.0f * fminf(pe, ge) - cd, 0.0f);
        den *= pe + ge + EPSF;
    }
    {
        float mp = 2.0f*(px*py - pz*pw)*dpx + (Ap - 2.0f*(px*px + pz*pz))*dpy + 2.0f*(py*pz + px*pw)*dpz;
        float mg = 2.0f*(gx*gy - gz*gw)*dgx + (Ag - 2.0f*(gx*gx + gz*gz))*dgy + 2.0f*(gy*gz + gx*gw)*dgz;
        float pe = sp * fabsf(mp), ge = sg * fabsf(mg);
        float cd = fabsf(p[1] - t[1]);
        num *= fmaxf(2.0f * fminf(pe, ge) - cd, 0.0f);
        den *= pe + ge + EPSF;
    }
    {
        float mp = 2.0f*(px*pz + py*pw)*dpx + 2.0f*(py*pz - px*pw)*dpy + (Ap - 2.0f*(px*px + py*py))*dpz;
        float mg = 2.0f*(gx*gz + gy*gw)*dgx + 2.0f*(gy*gz - gx*gw)*dgy + (Ag - 2.0f*(gx*gx + gy*gy))*dgz;
        float pe = sp * fabsf(mp), ge = sg * fabsf(mg);
        float cd = fabsf(p[2] - t[2]);
        num *= fmaxf(2.0f * fminf(pe, ge) - cd, 0.0f);
        den *= pe + ge + EPSF;
    }
    ov_acc += __fdividef(num * rot_align, den);
}

__global__ __launch_bounds__(THREADS, 4) void hl_fused_kernel(
    const float* __restrict__ preds,
    const float* __restrict__ targets,
    float* __restrict__ out)
{
    __shared__ unsigned int s_idx[2];   // double-buffered future unit index

    const int tid = threadIdx.x;
    const int bid = blockIdx.x;

    const float2* __restrict__ p2 = reinterpret_cast<const float2*>(preds);
    const float2* __restrict__ t2 = reinterpret_cast<const float2*>(targets);

    float l1_sum = 0.0f;
    float ov     = 0.0f;

    // unit 0 for this CTA is pre-assigned
    unsigned int u_cur = (unsigned int)bid;

    // A buffer <- sub0 of current unit
    float2 ap[5], at[5];
    {
        int r0 = (int)u_cur * UNIT_ROWS + tid;
        if (r0 < NROWS) load_row(p2, t2, r0, ap, at);
    }

    // fetch next unit index
    if (tid == 0) s_idx[0] = atomicAdd(&g_work, 1u);
    __syncthreads();
    unsigned int u_next = s_idx[0];

    int k = 0;
    while (u_cur < NUNITS) {
        const int base = (int)u_cur * UNIT_ROWS;

        // load B <- sub1 of current unit (overlaps sub0 math below)
        float2 bp[5], bt[5];
        const int  r1   = base + 256 + tid;
        const bool b_ok = (r1 < NROWS);
        if (b_ok) load_row(p2, t2, r1, bp, bt);

        // fetch the unit after u_next (latency hides under math)
        if (tid == 0) s_idx[(k + 1) & 1] = atomicAdd(&g_work, 1u);

        // compute sub0
        {
            const int r0 = base + tid;
            if (r0 < NROWS) row_math(ap, at, l1_sum, ov);
        }

        // load A <- sub0 of next unit (overlaps sub1 math below)
        if (u_next < NUNITS) {
            const int nr0 = (int)u_next * UNIT_ROWS + tid;
            if (nr0 < NROWS) load_row(p2, t2, nr0, ap, at);
        }

        // compute sub1
        if (b_ok) row_math(bp, bt, l1_sum, ov);

        __syncthreads();   // publish s_idx slot; order slot reuse

        u_cur  = u_next;
        u_next = s_idx[(k + 1) & 1];
        k++;
    }

    // ---- block reduction ----
    #pragma unroll
    for (int off = 16; off > 0; off >>= 1) {
        l1_sum += __shfl_down_sync(0xFFFFFFFFu, l1_sum, off);
        ov     += __shfl_down_sync(0xFFFFFFFFu, ov, off);
    }
    __shared__ float warp_l1[THREADS / 32];
    __shared__ float warp_ov[THREADS / 32];
    const int lane = tid & 31;
    const int wid  = tid >> 5;
    if (lane == 0) { warp_l1[wid] = l1_sum; warp_ov[wid] = ov; }
    __syncthreads();

    if (wid == 0) {
        float a = (lane < THREADS / 32) ? warp_l1[lane] : 0.0f;
        float b = (lane < THREADS / 32) ? warp_ov[lane] : 0.0f;
        #pragma unroll
        for (int off = 4; off > 0; off >>= 1) {
            a += __shfl_down_sync(0xFFFFFFFFu, a, off);
            b += __shfl_down_sync(0xFFFFFFFFu, b, off);
        }
        if (lane == 0) {
            atomicAdd(&g_acc[0], (double)a);
            atomicAdd(&g_acc[1], (double)b);
            __threadfence();
            unsigned int ticket = atomicAdd(&g_ticket, 1u);
            if (ticket == (unsigned int)(NBLOCKS - 1)) {
                double s0 = *((volatile double*)&g_acc[0]);
                double s1 = *((volatile double*)&g_acc[1]);
                double param_loss = s0 / ((double)NROWS * 10.0);
                double mean_ov    = s1 / (double)NROWS;
                out[0] = (float)(param_loss + 0.5 * (1.0 - mean_ov));
                // self-reset for next graph replay
                *((volatile double*)&g_acc[0]) = 0.0;
                *((volatile double*)&g_acc[1]) = 0.0;
                g_work = NBLOCKS;
                __threadfence();
                g_ticket = 0;
                __threadfence();
            }
        }
    }
}

extern "C" void kernel_launch(void* const* d_in, const int* in_sizes, int n_in,
                              void* d_out, int out_size) {
    const float* preds   = (const float*)d_in[0];
    const float* targets = (const float*)d_in[1];
    float* out = (float*)d_out;

    hl_fused_kernel<<<NBLOCKS, THREADS>>>(preds, targets, out);
}